// round 14
// baseline (speedup 1.0000x reference)
#include <cuda_runtime.h>

#define LAT 64
#define QB 256           // main block threads (2 lanes per query, 128 queries/block)
#define OSPLIT 37
#define CHUNK 56         // 37*56 = 2072 >= 2048; static smem ~29.8KB < 48KB default
#define MAXN 4096

// scratch (static device arrays; no allocation allowed)
__device__ float4 g_aq[MAXN * (LAT / 4)];
__device__ float4 g_bo[MAXN * (LAT / 4)];
__device__ float4 g_v [MAXN * (LAT / 4)];
__device__ float  g_pnum[(size_t)OSPLIT * LAT * MAXN];
__device__ float  g_pden[OSPLIT * MAXN];

__device__ __forceinline__ unsigned long long pk2(float a, float b) {
    unsigned long long r;
    asm("mov.b64 %0, {%1, %2};" : "=l"(r) : "f"(a), "f"(b));
    return r;
}
__device__ __forceinline__ void upk2(unsigned long long v, float& a, float& b) {
    asm("mov.b64 {%0, %1}, %2;" : "=f"(a), "=f"(b) : "l"(v));
}
__device__ __forceinline__ unsigned long long ffma2(unsigned long long a,
                                                    unsigned long long b,
                                                    unsigned long long c) {
    unsigned long long d;
    asm("fma.rn.f32x2 %0, %1, %2, %3;" : "=l"(d) : "l"(a), "l"(b), "l"(c));
    return d;
}
__device__ __forceinline__ unsigned long long fadd2(unsigned long long a,
                                                    unsigned long long b) {
    unsigned long long d;
    asm("add.rn.f32x2 %0, %1, %2;" : "=l"(d) : "l"(a), "l"(b));
    return d;
}

// ---------------------------------------------------------------------------
// prep v2: one warp per row, 4 rows per 128-thread block, 512 blocks.
// Lane ln owns output columns (2ln, 2ln+1). Wv/W1 read via __ldg (L1-resident
// after first touch; all blocks share the same 16KB). No block barriers.
// ---------------------------------------------------------------------------
__global__ __launch_bounds__(128) void prep_kernel(
        const float* __restrict__ h_obs,
        const float* __restrict__ pos_obs,
        const float* __restrict__ pos_query,
        const float* __restrict__ W1,
        const float* __restrict__ b1,
        const float* __restrict__ Wv,
        const float* __restrict__ bv,
        int N_q, int N_o) {
    __shared__ float hs[4][LAT];

    const int w  = threadIdx.x >> 5;
    const int ln = threadIdx.x & 31;
    const int row = blockIdx.x * 4 + w;

    const bool is_o = (row < N_o);
    if (is_o) {
        hs[w][ln]      = h_obs[row * LAT + ln];
        hs[w][ln + 32] = h_obs[row * LAT + 32 + ln];
    }
    __syncwarp();

    const float2* W12 = (const float2*)W1;

    if (is_o) {
        // v = h_obs @ Wv + bv : 2 output columns per lane
        const float2* Wv2 = (const float2*)Wv;
        float2 a = ((const float2*)bv)[ln];
        #pragma unroll 16
        for (int k = 0; k < LAT; ++k) {
            float h = hs[w][k];
            float2 wv = __ldg(&Wv2[k * 32 + ln]);
            a.x = fmaf(h, wv.x, a.x);
            a.y = fmaf(h, wv.y, a.y);
        }
        ((float2*)g_v)[row * 32 + ln] = a;

        float px = pos_obs[row * 3 + 0];
        float py = pos_obs[row * 3 + 1];
        float pz = pos_obs[row * 3 + 2];
        float2 w3 = __ldg(&W12[3 * 32 + ln]);
        float2 w4 = __ldg(&W12[4 * 32 + ln]);
        float2 w5 = __ldg(&W12[5 * 32 + ln]);
        float2 w6 = __ldg(&W12[6 * 32 + ln]);
        float2 w7 = __ldg(&W12[7 * 32 + ln]);
        float2 w8 = __ldg(&W12[8 * 32 + ln]);
        float2 bb = ((const float2*)b1)[ln];
        float2 r;
        r.x = bb.x + px * (w3.x - w6.x) + py * (w4.x - w7.x) + pz * (w5.x - w8.x);
        r.y = bb.y + px * (w3.y - w6.y) + py * (w4.y - w7.y) + pz * (w5.y - w8.y);
        ((float2*)g_bo)[row * 32 + ln] = r;
    }

    if (row < N_q) {
        float px = pos_query[row * 3 + 0];
        float py = pos_query[row * 3 + 1];
        float pz = pos_query[row * 3 + 2];
        float2 w0 = __ldg(&W12[0 * 32 + ln]);
        float2 w1 = __ldg(&W12[1 * 32 + ln]);
        float2 w2 = __ldg(&W12[2 * 32 + ln]);
        float2 w6 = __ldg(&W12[6 * 32 + ln]);
        float2 w7 = __ldg(&W12[7 * 32 + ln]);
        float2 w8 = __ldg(&W12[8 * 32 + ln]);
        float2 a;
        a.x = px * (w0.x + w6.x) + py * (w1.x + w7.x) + pz * (w2.x + w8.x);
        a.y = px * (w0.y + w6.y) + py * (w1.y + w7.y) + pz * (w2.y + w8.y);
        ((float2*)g_aq)[row * 32 + ln] = a;
    }
}

// ---------------------------------------------------------------------------
// main v2: 2 lanes per query. Lane pair (ln, ln^16) each owns 32 of 64
// latents; partial logits combined via shfl_xor(16) (bitwise-identical on both
// lanes since FP add commutes). Each lane accumulates only its 32 v-latents.
// 256 threads = 128 queries per block. Static smem (<48KB, no attribute call).
// Grid 16 x 37 = 592 blocks = exactly 2 full waves at occ 2 on 148 SMs.
// ---------------------------------------------------------------------------
__global__ __launch_bounds__(QB, 2) void main_kernel(
        const float* __restrict__ pos_query,
        const float* __restrict__ pos_obs,
        const float* __restrict__ W2,
        int N_q, int N_o) {
    __shared__ float4 bo_s[CHUNK * 16];
    __shared__ float4 v_s [CHUNK * 16];
    __shared__ float4 pos_s[CHUNK];
    __shared__ unsigned long long w2s[LAT / 2];

    const int tid = threadIdx.x;
    const int o0  = blockIdx.y * CHUNK;
    int oCount = N_o - o0;
    if (oCount > CHUNK) oCount = CHUNK;
    if (oCount < 0) oCount = 0;

    const int nv = oCount * (LAT / 4);
    for (int i = tid; i < nv; i += QB) {
        bo_s[i] = g_bo[o0 * (LAT / 4) + i];
        v_s[i]  = g_v [o0 * (LAT / 4) + i];
    }
    for (int i = tid; i < oCount; i += QB) {
        int o = o0 + i;
        pos_s[i] = make_float4(pos_obs[o * 3 + 0], pos_obs[o * 3 + 1],
                               pos_obs[o * 3 + 2], 0.f);
    }
    if (tid < LAT / 2) w2s[tid] = pk2(W2[2 * tid], W2[2 * tid + 1]);
    __syncthreads();

    const int warp = tid >> 5;
    const int ln   = tid & 31;
    const int hh   = ln >> 4;               // half: 0 -> l[0,32), 1 -> l[32,64)
    const int qi   = ln & 15;
    int q = blockIdx.x * 128 + warp * 16 + qi;
    const bool valid = (q < N_q);
    if (!valid) q = 0;                      // clamp; lane still participates in shfl

    // this lane's 32 latents of aq
    float aq[32];
    #pragma unroll
    for (int j = 0; j < 8; ++j) {
        float4 t = g_aq[q * 16 + hh * 8 + j];
        aq[4 * j + 0] = t.x; aq[4 * j + 1] = t.y;
        aq[4 * j + 2] = t.z; aq[4 * j + 3] = t.w;
    }
    const float qx = pos_query[q * 3 + 0];
    const float qy = pos_query[q * 3 + 1];
    const float qz = pos_query[q * 3 + 2];

    const unsigned long long* w2h = &w2s[hh * 16];

    unsigned long long acc[16];
    #pragma unroll
    for (int j = 0; j < 16; ++j) acc[j] = 0ull;
    float den = 0.f;

    for (int o = 0; o < oCount; ++o) {
        float4 p = pos_s[o];
        float dx = qx - p.x, dy = qy - p.y, dz = qz - p.z;
        float d2 = fmaf(dx, dx, fmaf(dy, dy, dz * dz));

        const float4* bo4 = &bo_s[o * 16 + hh * 8];
        unsigned long long l0 = 0, l1 = 0;
        #pragma unroll
        for (int j = 0; j < 8; ++j) {
            float4 b = bo4[j];
            float h0 = fmaxf(aq[4 * j + 0] + b.x, 0.f);
            float h1 = fmaxf(aq[4 * j + 1] + b.y, 0.f);
            float h2 = fmaxf(aq[4 * j + 2] + b.z, 0.f);
            float h3 = fmaxf(aq[4 * j + 3] + b.w, 0.f);
            l0 = ffma2(pk2(h0, h1), w2h[2 * j + 0], l0);
            l1 = ffma2(pk2(h2, h3), w2h[2 * j + 1], l1);
        }
        unsigned long long ls = fadd2(l0, l1);
        float xa, xb;
        upk2(ls, xa, xb);
        float part = xa + xb;
        float other = __shfl_xor_sync(0xFFFFFFFFu, part, 16);
        float logit = part + other;         // commutative add: identical both lanes

        // radius mask; unnormalized exp (logits are O(1), no overflow risk)
        float e = (d2 <= 0.25f) ? __expf(logit) : 0.f;
        den += e;

        unsigned long long e2 = pk2(e, e);
        const float4* v4 = &v_s[o * 16 + hh * 8];
        #pragma unroll
        for (int j = 0; j < 8; ++j) {
            float4 vv = v4[j];
            acc[2 * j + 0] = ffma2(e2, pk2(vv.x, vv.y), acc[2 * j + 0]);
            acc[2 * j + 1] = ffma2(e2, pk2(vv.z, vv.w), acc[2 * j + 1]);
        }
    }

    if (valid) {
        const int s = blockIdx.y;
        #pragma unroll
        for (int j = 0; j < 16; ++j) {
            float a, b;
            upk2(acc[j], a, b);
            int l = hh * 32 + 2 * j;
            g_pnum[(size_t)(s * LAT + l + 0) * N_q + q] = a;  // coalesced over q
            g_pnum[(size_t)(s * LAT + l + 1) * N_q + q] = b;
        }
        if (hh == 0) g_pden[s * N_q + q] = den;
    }
}

// ---------------------------------------------------------------------------
// combine: each thread sums OSPLIT partials for 4 l's of one query (fully
// unrolled independent coalesced loads -> high MLP), normalizes, stores float4.
// ---------------------------------------------------------------------------
__global__ __launch_bounds__(256) void combine_kernel(float* __restrict__ out,
                                                      int N_q) {
    int t = blockIdx.x * blockDim.x + threadIdx.x;
    int total = (LAT / 4) * N_q;
    if (t >= total) return;
    int l4 = t / N_q;
    int q  = t - l4 * N_q;

    float n0 = 0.f, n1 = 0.f, n2 = 0.f, n3 = 0.f, den = 0.f;
    #pragma unroll
    for (int s = 0; s < OSPLIT; ++s) {
        size_t base = (size_t)(s * LAT + 4 * l4) * N_q + q;
        n0 += g_pnum[base];
        n1 += g_pnum[base + (size_t)N_q];
        n2 += g_pnum[base + (size_t)2 * N_q];
        n3 += g_pnum[base + (size_t)3 * N_q];
        den += g_pden[s * N_q + q];
    }
    float inv = 1.f / den;
    ((float4*)out)[q * (LAT / 4) + l4] =
        make_float4(n0 * inv, n1 * inv, n2 * inv, n3 * inv);
}

extern "C" void kernel_launch(void* const* d_in, const int* in_sizes, int n_in,
                              void* d_out, int out_size) {
    const float* h_obs     = (const float*)d_in[0];
    // d_in[1] = x_obs: unused by the reference computation
    const float* pos_obs   = (const float*)d_in[2];
    const float* pos_query = (const float*)d_in[3];
    const float* W1        = (const float*)d_in[4];
    const float* b1        = (const float*)d_in[5];
    const float* W2        = (const float*)d_in[6];
    // d_in[7] = b2: uniform logit shift, cancels in softmax
    const float* Wv        = (const float*)d_in[8];
    const float* bv        = (const float*)d_in[9];

    const int N_o = in_sizes[0] / LAT;
    const int N_q = in_sizes[3] / 3;
    float* out = (float*)d_out;

    int R = (N_q > N_o) ? N_q : N_o;
    prep_kernel<<<(R + 3) / 4, 128>>>(h_obs, pos_obs, pos_query, W1, b1, Wv,
                                      bv, N_q, N_o);

    dim3 grid((N_q + 127) / 128, OSPLIT);
    main_kernel<<<grid, QB>>>(pos_query, pos_obs, W2, N_q, N_o);

    int tot = (LAT / 4) * N_q;
    combine_kernel<<<(tot + 255) / 256, 256>>>(out, N_q);
}

// round 17
// speedup vs baseline: 1.1752x; 1.1752x over previous
#include <cuda_runtime.h>

#define LAT 64
#define QB 128
#define OSPLIT 18
#define MAXN 4096

// scratch (static device arrays; no allocation allowed)
__device__ float4 g_aq[MAXN * (LAT / 4)];
__device__ float4 g_bo[MAXN * (LAT / 4)];
__device__ float  g_pnum[(size_t)OSPLIT * LAT * MAXN];   // [s][q][l]
__device__ float  g_pden[OSPLIT * MAXN];

__device__ __forceinline__ unsigned long long pk2(float a, float b) {
    unsigned long long r;
    asm("mov.b64 %0, {%1, %2};" : "=l"(r) : "f"(a), "f"(b));
    return r;
}
__device__ __forceinline__ void upk2(unsigned long long v, float& a, float& b) {
    asm("mov.b64 {%0, %1}, %2;" : "=f"(a), "=f"(b) : "l"(v));
}
__device__ __forceinline__ unsigned long long ffma2(unsigned long long a,
                                                    unsigned long long b,
                                                    unsigned long long c) {
    unsigned long long d;
    asm("fma.rn.f32x2 %0, %1, %2, %3;" : "=l"(d) : "l"(a), "l"(b), "l"(c));
    return d;
}
__device__ __forceinline__ unsigned long long fadd2(unsigned long long a,
                                                    unsigned long long b) {
    unsigned long long d;
    asm("add.rn.f32x2 %0, %1, %2;" : "=l"(d) : "l"(a), "l"(b));
    return d;
}
// packed ReLU: fadd2 result -> per-half FMNMX (alu pipe) -> repacked pair
__device__ __forceinline__ unsigned long long relu2(unsigned long long x) {
    float a, b;
    upk2(x, a, b);
    a = fmaxf(a, 0.f);
    b = fmaxf(b, 0.f);
    return pk2(a, b);
}

// ---------------------------------------------------------------------------
// prep v3 (tiny): aq and bo only — the v-projection is algebraically folded
// into combine (softmax weights sum to 1, so weights@(h@Wv+bv) =
// (weights@h)@Wv + bv). One warp per row, 4 rows/block.
// ---------------------------------------------------------------------------
__global__ __launch_bounds__(128) void prep_kernel(
        const float* __restrict__ pos_obs,
        const float* __restrict__ pos_query,
        const float* __restrict__ W1,
        const float* __restrict__ b1,
        int N_q, int N_o) {
    const int w  = threadIdx.x >> 5;
    const int ln = threadIdx.x & 31;
    const int row = blockIdx.x * 4 + w;

    const float2* W12 = (const float2*)W1;

    if (row < N_o) {
        float px = pos_obs[row * 3 + 0];
        float py = pos_obs[row * 3 + 1];
        float pz = pos_obs[row * 3 + 2];
        float2 w3 = __ldg(&W12[3 * 32 + ln]);
        float2 w4 = __ldg(&W12[4 * 32 + ln]);
        float2 w5 = __ldg(&W12[5 * 32 + ln]);
        float2 w6 = __ldg(&W12[6 * 32 + ln]);
        float2 w7 = __ldg(&W12[7 * 32 + ln]);
        float2 w8 = __ldg(&W12[8 * 32 + ln]);
        float2 bb = ((const float2*)b1)[ln];
        float2 r;
        r.x = bb.x + px * (w3.x - w6.x) + py * (w4.x - w7.x) + pz * (w5.x - w8.x);
        r.y = bb.y + px * (w3.y - w6.y) + py * (w4.y - w7.y) + pz * (w5.y - w8.y);
        ((float2*)g_bo)[row * 32 + ln] = r;
    }
    if (row < N_q) {
        float px = pos_query[row * 3 + 0];
        float py = pos_query[row * 3 + 1];
        float pz = pos_query[row * 3 + 2];
        float2 w0 = __ldg(&W12[0 * 32 + ln]);
        float2 w1 = __ldg(&W12[1 * 32 + ln]);
        float2 w2 = __ldg(&W12[2 * 32 + ln]);
        float2 w6 = __ldg(&W12[6 * 32 + ln]);
        float2 w7 = __ldg(&W12[7 * 32 + ln]);
        float2 w8 = __ldg(&W12[8 * 32 + ln]);
        float2 a;
        a.x = px * (w0.x + w6.x) + py * (w1.x + w7.x) + pz * (w2.x + w8.x);
        a.y = px * (w0.y + w6.y) + py * (w1.y + w7.y) + pz * (w2.y + w8.y);
        ((float2*)g_aq)[row * 32 + ln] = a;
    }
}

// ---------------------------------------------------------------------------
// main v4: thread-per-query. Hidden layer: fadd2 (fma pipe) + scalar FMNMX
// (alu pipe, overlaps) + ffma2 dot. Accumulates raw h_obs weighted by
// unnormalized exp. Partials written [s][q][l] as 16 STG.128.
// fma-pipe ops/warp-o: 32 fadd2 + 32 ffma2 + 32 ffma2 = 96 (was 128).
// ---------------------------------------------------------------------------
__global__ __launch_bounds__(QB, 2) void main_kernel(
        const float* __restrict__ pos_query,
        const float* __restrict__ pos_obs,
        const float* __restrict__ h_obs,
        const float* __restrict__ W2,
        int N_q, int N_o, int chunk) {
    extern __shared__ char smem_raw[];
    float4* bo4   = (float4*)smem_raw;                 // chunk*16
    float4* v4    = bo4 + (size_t)chunk * 16;          // chunk*16 (raw h_obs)
    float4* pos_s = v4 + (size_t)chunk * 16;           // chunk
    unsigned long long* w2s = (unsigned long long*)(pos_s + chunk);  // 32

    const int tid = threadIdx.x;
    const int o0  = blockIdx.y * chunk;
    int oCount = N_o - o0;
    if (oCount > chunk) oCount = chunk;
    if (oCount < 0) oCount = 0;

    const float4* hg = (const float4*)h_obs;
    const int nv = oCount * (LAT / 4);
    for (int i = tid; i < nv; i += QB) {
        bo4[i] = g_bo[o0 * (LAT / 4) + i];
        v4[i]  = hg  [o0 * (LAT / 4) + i];
    }
    for (int i = tid; i < oCount; i += QB) {
        int o = o0 + i;
        pos_s[i] = make_float4(pos_obs[o * 3 + 0], pos_obs[o * 3 + 1],
                               pos_obs[o * 3 + 2], 0.f);
    }
    if (tid < 32) w2s[tid] = pk2(W2[2 * tid], W2[2 * tid + 1]);
    __syncthreads();

    int q = blockIdx.x * QB + tid;
    if (q >= N_q) return;

    // aq packed: 32 u64 (64 latents)
    unsigned long long aq2[32];
    const ulonglong2* ga = (const ulonglong2*)g_aq;
    #pragma unroll
    for (int j = 0; j < 16; ++j) {
        ulonglong2 u = ga[q * 16 + j];
        aq2[2 * j + 0] = u.x;
        aq2[2 * j + 1] = u.y;
    }
    const float qx = pos_query[q * 3 + 0];
    const float qy = pos_query[q * 3 + 1];
    const float qz = pos_query[q * 3 + 2];

    unsigned long long acc[32];
    #pragma unroll
    for (int j = 0; j < 32; ++j) acc[j] = 0ull;
    float den = 0.f;

    for (int o = 0; o < oCount; ++o) {
        float4 p = pos_s[o];
        float dx = qx - p.x, dy = qy - p.y, dz = qz - p.z;
        float d2 = fmaf(dx, dx, fmaf(dy, dy, dz * dz));

        const ulonglong2* b2 = (const ulonglong2*)(bo4 + (size_t)o * 16);
        unsigned long long L0 = 0, L1 = 0, L2 = 0, L3 = 0;
        #pragma unroll
        for (int j = 0; j < 16; ++j) {
            ulonglong2 b = b2[j];
            unsigned long long h0 = relu2(fadd2(aq2[2 * j + 0], b.x));
            unsigned long long h1 = relu2(fadd2(aq2[2 * j + 1], b.y));
            if (j & 1) {
                L2 = ffma2(h0, w2s[2 * j + 0], L2);
                L3 = ffma2(h1, w2s[2 * j + 1], L3);
            } else {
                L0 = ffma2(h0, w2s[2 * j + 0], L0);
                L1 = ffma2(h1, w2s[2 * j + 1], L1);
            }
        }
        unsigned long long ls = fadd2(fadd2(L0, L1), fadd2(L2, L3));
        float xa, xb;
        upk2(ls, xa, xb);
        float logit = xa + xb;

        // radius mask; unnormalized exp (logits are O(1), no overflow risk)
        float e = (d2 <= 0.25f) ? __expf(logit) : 0.f;
        den += e;

        unsigned long long e2 = pk2(e, e);
        const ulonglong2* vv = (const ulonglong2*)(v4 + (size_t)o * 16);
        #pragma unroll
        for (int j = 0; j < 16; ++j) {
            ulonglong2 V = vv[j];
            acc[2 * j + 0] = ffma2(e2, V.x, acc[2 * j + 0]);
            acc[2 * j + 1] = ffma2(e2, V.y, acc[2 * j + 1]);
        }
    }

    // write partials [s][q][l] as 16 STG.128
    float4* outp = (float4*)&g_pnum[((size_t)blockIdx.y * N_q + q) * LAT];
    #pragma unroll
    for (int j = 0; j < 16; ++j) {
        float a, b, c, d;
        upk2(acc[2 * j + 0], a, b);
        upk2(acc[2 * j + 1], c, d);
        outp[j] = make_float4(a, b, c, d);
    }
    g_pden[blockIdx.y * N_q + q] = den;
}

// ---------------------------------------------------------------------------
// combine v3: sum partials over s (coalesced float4), then apply the folded
// value projection: out[q] = (n[q] @ Wv) / den[q] + bv. 16 queries per block.
// ---------------------------------------------------------------------------
__global__ __launch_bounds__(128) void combine_kernel(
        float* __restrict__ out,
        const float* __restrict__ Wv,
        const float* __restrict__ bv,
        int N_q) {
    __shared__ float4 wv_s[LAT * 16];     // Wv row-major, 16KB
    __shared__ float  n_s[16 * LAT];      // summed numerators
    __shared__ float  den_s[16];

    const int t  = threadIdx.x;
    const int q0 = blockIdx.x * 16;

    const float4* Wv4 = (const float4*)Wv;
    #pragma unroll
    for (int i = 0; i < 8; ++i) wv_s[t + i * 128] = Wv4[t + i * 128];

    // phase 1: n[q][l] = sum_s pnum[s][q][l]  (float4 granularity, coalesced)
    const float4* pn4 = (const float4*)g_pnum;
    #pragma unroll
    for (int r = 0; r < 2; ++r) {
        int idx = t + r * 128;            // 0..255 : q = idx>>4, j = idx&15
        int q = idx >> 4, j = idx & 15;
        float4 s = make_float4(0.f, 0.f, 0.f, 0.f);
        if (q0 + q < N_q) {
            #pragma unroll
            for (int sp = 0; sp < OSPLIT; ++sp) {
                float4 pv = pn4[((size_t)sp * N_q + q0 + q) * 16 + j];
                s.x += pv.x; s.y += pv.y; s.z += pv.z; s.w += pv.w;
            }
        }
        ((float4*)n_s)[idx] = s;
    }
    if (t < 16) {
        float d = 0.f;
        if (q0 + t < N_q) {
            #pragma unroll
            for (int sp = 0; sp < OSPLIT; ++sp) d += g_pden[sp * N_q + q0 + t];
        }
        den_s[t] = (d != 0.f) ? d : 1.f;
    }
    __syncthreads();

    // phase 2: out[q][8g..8g+7] = (sum_l n[q][l]*Wv[l][...]) / den + bv
    const int q = t >> 3;
    const int g = t & 7;
    if (q0 + q >= N_q) return;

    float4 o0 = make_float4(0.f, 0.f, 0.f, 0.f);
    float4 o1 = make_float4(0.f, 0.f, 0.f, 0.f);
    #pragma unroll 8
    for (int l = 0; l < LAT; ++l) {
        float nl = n_s[q * LAT + l];
        float4 wA = wv_s[l * 16 + 2 * g + 0];
        float4 wB = wv_s[l * 16 + 2 * g + 1];
        o0.x = fmaf(nl, wA.x, o0.x); o0.y = fmaf(nl, wA.y, o0.y);
        o0.z = fmaf(nl, wA.z, o0.z); o0.w = fmaf(nl, wA.w, o0.w);
        o1.x = fmaf(nl, wB.x, o1.x); o1.y = fmaf(nl, wB.y, o1.y);
        o1.z = fmaf(nl, wB.z, o1.z); o1.w = fmaf(nl, wB.w, o1.w);
    }
    float inv = 1.f / den_s[q];
    float4 bA = ((const float4*)bv)[2 * g + 0];
    float4 bB = ((const float4*)bv)[2 * g + 1];
    float4* out4 = (float4*)out;
    out4[(q0 + q) * 16 + 2 * g + 0] =
        make_float4(o0.x * inv + bA.x, o0.y * inv + bA.y,
                    o0.z * inv + bA.z, o0.w * inv + bA.w);
    out4[(q0 + q) * 16 + 2 * g + 1] =
        make_float4(o1.x * inv + bB.x, o1.y * inv + bB.y,
                    o1.z * inv + bB.z, o1.w * inv + bB.w);
}

extern "C" void kernel_launch(void* const* d_in, const int* in_sizes, int n_in,
                              void* d_out, int out_size) {
    const float* h_obs     = (const float*)d_in[0];
    // d_in[1] = x_obs: unused by the reference computation
    const float* pos_obs   = (const float*)d_in[2];
    const float* pos_query = (const float*)d_in[3];
    const float* W1        = (const float*)d_in[4];
    const float* b1        = (const float*)d_in[5];
    const float* W2        = (const float*)d_in[6];
    // d_in[7] = b2: uniform logit shift, cancels in softmax
    const float* Wv        = (const float*)d_in[8];
    const float* bv        = (const float*)d_in[9];

    const int N_o = in_sizes[0] / LAT;
    const int N_q = in_sizes[3] / 3;
    float* out = (float*)d_out;

    int R = (N_q > N_o) ? N_q : N_o;
    prep_kernel<<<(R + 3) / 4, 128>>>(pos_obs, pos_query, W1, b1, N_q, N_o);

    const int chunk = (N_o + OSPLIT - 1) / OSPLIT;   // 114 for N_o=2048
    size_t smem = (size_t)chunk * 16 * sizeof(float4) * 2   // bo + v(h_obs)
                + (size_t)chunk * sizeof(float4)            // pos_s
                + 32 * sizeof(unsigned long long);          // w2s
    static int smem_set = 0;
    if (!smem_set) {
        cudaFuncSetAttribute(main_kernel,
                             cudaFuncAttributeMaxDynamicSharedMemorySize,
                             (int)smem);
        smem_set = 1;
    }
    dim3 grid((N_q + QB - 1) / QB, OSPLIT);
    main_kernel<<<grid, QB, smem>>>(pos_query, pos_obs, h_obs, W2,
                                    N_q, N_o, chunk);

    combine_kernel<<<(N_q + 15) / 16, 128>>>(out, Wv, bv, N_q);
}